// round 3
// baseline (speedup 1.0000x reference)
#include <cuda_runtime.h>

// LIF recurrence: v = alpha*v + beta*c; spike = (v >= 1); v = spike ? 0 : v.
// Sequential over T=2048, parallel over N=32768.
// Output: out[0 : T*N] = spikes, out[T*N : 2*T*N] = post-reset voltages.
//
// HBM-bound (768 MB mandatory traffic). R2 measured DRAM=58% with PF=8
// (1.0 MB outstanding vs ~1.7 MB needed). PF=16 -> 2.0 MB outstanding to
// saturate HBM with only 1024 warps.

#define T_STEPS 2048
#define N_NEUR  32768
#define PF      16         // prefetch/pipeline depth (steps)

__global__ void __launch_bounds__(128, 2)
lif_kernel(const float* __restrict__ cur,
           const float* __restrict__ v0,
           float* __restrict__ out)
{
    const int n = blockIdx.x * blockDim.x + threadIdx.x;

    // Match reference f32 constants: alpha = f32(exp(-1/20)), beta = f32(1 - alpha)
    const float alpha = (float)0.9512294245007140;
    const float beta  = (float)(1.0 - 0.9512294245007140);

    float v = v0[n];

    const float* cp = cur + n;
    float* sp = out + n;                                  // spikes
    float* vp = out + (size_t)T_STEPS * N_NEUR + n;       // voltages

    // Prime the pipeline with steps 0..PF-1
    float buf[PF];
#pragma unroll
    for (int i = 0; i < PF; ++i)
        buf[i] = cp[(size_t)i * N_NEUR];
    cp += (size_t)PF * N_NEUR;

    // Main loop: issue next PF loads (front-batched -> MLP=16),
    // then compute/store the current PF steps.
    for (int t = 0; t < T_STEPS - PF; t += PF) {
        float nxt[PF];
#pragma unroll
        for (int i = 0; i < PF; ++i)
            nxt[i] = cp[(size_t)i * N_NEUR];
        cp += (size_t)PF * N_NEUR;

#pragma unroll
        for (int i = 0; i < PF; ++i) {
            // v = alpha*v + beta*c, explicitly unfused to match reference rounding
            v = __fadd_rn(__fmul_rn(alpha, v), __fmul_rn(beta, buf[i]));
            const bool fire = (v >= 1.0f);
            const float s = fire ? 1.0f : 0.0f;
            v = fire ? 0.0f : v;
            *sp = s;
            *vp = v;
            sp += N_NEUR;
            vp += N_NEUR;
        }

#pragma unroll
        for (int i = 0; i < PF; ++i)
            buf[i] = nxt[i];
    }

    // Drain the final PF steps
#pragma unroll
    for (int i = 0; i < PF; ++i) {
        v = __fadd_rn(__fmul_rn(alpha, v), __fmul_rn(beta, buf[i]));
        const bool fire = (v >= 1.0f);
        const float s = fire ? 1.0f : 0.0f;
        v = fire ? 0.0f : v;
        *sp = s;
        *vp = v;
        sp += N_NEUR;
        vp += N_NEUR;
    }
}

extern "C" void kernel_launch(void* const* d_in, const int* in_sizes, int n_in,
                              void* d_out, int out_size)
{
    const float* currents = (const float*)d_in[0];   // (T, N) float32
    const float* v0       = (const float*)d_in[1];   // (N,)  float32
    float* out            = (float*)d_out;           // 2*T*N float32

    lif_kernel<<<N_NEUR / 128, 128>>>(currents, v0, out);
}

// round 4
// speedup vs baseline: 1.0994x; 1.0994x over previous
#include <cuda_runtime.h>

// LIF recurrence: v = alpha*v + beta*c; spike = (v >= 1); v = spike ? 0 : v.
// Sequential over T=2048, parallel over N=32768.
// Output: out[0 : T*N] = spikes, out[T*N : 2*T*N] = post-reset voltages.
//
// HBM-bound (768 MB mandatory). R2/R3 showed register-based prefetch caps at
// ~1 MB outstanding (DRAM=58%) because ptxas won't materialize deep register
// buffers. This version pipelines the current stream through SHARED MEMORY
// with cp.async (LDGSTS): 32 stages x 512 B per CTA, 4 commit-groups of 8
// steps => ~4.7 MB chip-wide in flight, zero register pressure.

#define T_STEPS 2048
#define N_NEUR  32768
#define BLOCK   128
#define STAGES  32                 // smem pipeline depth (steps)
#define GRP     8                  // steps per cp.async commit group
#define NGRP    (STAGES / GRP)     // 4 groups in flight

__device__ __forceinline__ void cp_async4(unsigned saddr, const float* gptr)
{
    asm volatile("cp.async.ca.shared.global [%0], [%1], 4;"
                 :: "r"(saddr), "l"(gptr));
}
__device__ __forceinline__ void cp_commit()
{
    asm volatile("cp.async.commit_group;");
}
__device__ __forceinline__ void cp_wait_allow3()
{
    asm volatile("cp.async.wait_group %0;" :: "n"(NGRP - 1));
}

__global__ void __launch_bounds__(BLOCK, 2)
lif_kernel(const float* __restrict__ cur,
           const float* __restrict__ v0,
           float* __restrict__ out)
{
    __shared__ float sbuf[STAGES * BLOCK];

    const int tid = threadIdx.x;
    const int n   = blockIdx.x * BLOCK + tid;

    // Match reference f32 constants: alpha = f32(exp(-1/20)), beta = f32(1 - alpha)
    const float alpha = (float)0.9512294245007140;
    const float beta  = (float)(1.0 - 0.9512294245007140);

    float v = v0[n];

    const float* cp = cur + n;
    float* sp = out + n;                                  // spikes
    float* vp = out + (size_t)T_STEPS * N_NEUR + n;       // voltages

    const unsigned sbase =
        (unsigned)__cvta_generic_to_shared(sbuf) + (unsigned)tid * 4u;

    // ---- Prime: issue all STAGES stages as NGRP commit groups ----
#pragma unroll
    for (int g = 0; g < NGRP; ++g) {
#pragma unroll
        for (int i = 0; i < GRP; ++i) {
            const int s = g * GRP + i;
            cp_async4(sbase + (unsigned)(s * BLOCK) * 4u,
                      cp + (size_t)s * N_NEUR);
        }
        cp_commit();
    }
    cp += (size_t)STAGES * N_NEUR;

    // ---- Main loop: one commit group (8 steps) per iteration ----
    for (int t = 0; t < T_STEPS; t += GRP) {
        cp_wait_allow3();                      // oldest group (steps t..t+7) ready

        const int slot = (t / GRP) & (NGRP - 1);   // group slot 0..3

        // Read this group's 8 currents from smem first...
        float c[GRP];
#pragma unroll
        for (int i = 0; i < GRP; ++i)
            c[i] = sbuf[(slot * GRP + i) * BLOCK + tid];

        // ...then reuse the slot for steps t+STAGES..t+STAGES+7.
        if (t + STAGES < T_STEPS) {
#pragma unroll
            for (int i = 0; i < GRP; ++i)
                cp_async4(sbase + (unsigned)((slot * GRP + i) * BLOCK) * 4u,
                          cp + (size_t)i * N_NEUR);
            cp += (size_t)GRP * N_NEUR;
        }
        cp_commit();                           // empty group near the tail is fine

        // Compute + store the 8 steps.
#pragma unroll
        for (int i = 0; i < GRP; ++i) {
            // v = alpha*v + beta*c, explicitly unfused to match reference rounding
            v = __fadd_rn(__fmul_rn(alpha, v), __fmul_rn(beta, c[i]));
            const bool fire = (v >= 1.0f);
            const float s = fire ? 1.0f : 0.0f;
            v = fire ? 0.0f : v;
            *sp = s;
            *vp = v;
            sp += N_NEUR;
            vp += N_NEUR;
        }
    }
}

extern "C" void kernel_launch(void* const* d_in, const int* in_sizes, int n_in,
                              void* d_out, int out_size)
{
    const float* currents = (const float*)d_in[0];   // (T, N) float32
    const float* v0       = (const float*)d_in[1];   // (N,)  float32
    float* out            = (float*)d_out;           // 2*T*N float32

    lif_kernel<<<N_NEUR / BLOCK, BLOCK>>>(currents, v0, out);
}